// round 2
// baseline (speedup 1.0000x reference)
#include <cuda_runtime.h>
#include <cuda_bf16.h>

// Inputs (metadata order):
//   d_in[0] input_values   float32 [1024]
//   d_in[1] weight_matrix  float32 [16384*16384] row-major
//   d_in[2] biases         float32 [16384]
//   d_in[3] act_ids        int32   [16384]   0=identity 1=relu 2=softsign
//   d_in[4] input_indices  int32   [1024]
//   d_in[5] output_indices int32   [256]
// Output: float32 [256]
//
// out[o] = act( sum_i in_vals[i] * W[in_idx[i], out_idx[o]] + bias[out_idx[o]] )
//
// Strategy: 2-kernel graph.
//  K1 (gather): grid = NUM_OUT*CHUNKS small CTAs (128 thr). Each CTA computes
//     the partial dot of one 128-row chunk for one output column and writes it
//     to a __device__ scratch slot. One scattered W load per thread, fine CTA
//     granularity -> near-perfect SM balance and deep MLP.
//  K2 (finalize): one CTA; each thread sums its output's chunk partials,
//     adds bias, applies the branchless activation select, writes d_out.

#define CHUNK_THREADS 128
#define MAX_PARTIALS  8192   // supports out_size*chunks up to 8192

__device__ float g_partials[MAX_PARTIALS];

__global__ void __launch_bounds__(CHUNK_THREADS)
gather_kernel(const float* __restrict__ in_vals,
              const float* __restrict__ W,
              const int*   __restrict__ in_idx,
              const int*   __restrict__ out_idx,
              int n_in, int chunks, long long N)
{
    const int c     = blockIdx.x;
    const int o     = c / chunks;          // output slot
    const int chunk = c - o * chunks;      // row-chunk within the dot product
    const int t     = threadIdx.x;
    const int i     = chunk * CHUNK_THREADS + t;

    const int j = __ldg(&out_idx[o]);      // column (uniform per CTA)

    float p = 0.0f;
    if (i < n_in) {
        const long long row = (long long)__ldg(&in_idx[i]);
        p = __ldg(&in_vals[i]) * __ldg(&W[row * N + (long long)j]);
    }

    // warp reduce (4 warps) then smem combine
    #pragma unroll
    for (int off = 16; off > 0; off >>= 1)
        p += __shfl_xor_sync(0xFFFFFFFFu, p, off);

    __shared__ float sm[CHUNK_THREADS / 32];
    const int lane = t & 31;
    const int wid  = t >> 5;
    if (lane == 0) sm[wid] = p;
    __syncthreads();

    if (t == 0) {
        float v = sm[0];
        #pragma unroll
        for (int w = 1; w < CHUNK_THREADS / 32; w++) v += sm[w];
        g_partials[c] = v;
    }
}

__global__ void finalize_kernel(const float* __restrict__ bias,
                                const int*   __restrict__ act_ids,
                                const int*   __restrict__ out_idx,
                                float*       __restrict__ out,
                                int n_out, int chunks)
{
    const int o = blockIdx.x * blockDim.x + threadIdx.x;
    if (o >= n_out) return;

    float v = 0.0f;
    const int base = o * chunks;
    #pragma unroll 8
    for (int k = 0; k < chunks; k++) v += g_partials[base + k];

    const int   j     = __ldg(&out_idx[o]);
    const float total = v + __ldg(&bias[j]);
    const int   a     = __ldg(&act_ids[j]);
    const float relu  = fmaxf(total, 0.0f);
    const float ssign = total / (1.0f + fabsf(total));
    out[o] = (a == 1) ? relu : ((a == 2) ? ssign : total);
}

extern "C" void kernel_launch(void* const* d_in, const int* in_sizes, int n_in_args,
                              void* d_out, int out_size)
{
    const float* in_vals = (const float*)d_in[0];
    const float* W       = (const float*)d_in[1];
    const float* bias    = (const float*)d_in[2];
    const int*   act_ids = (const int*)  d_in[3];
    const int*   in_idx  = (const int*)  d_in[4];
    const int*   out_idx = (const int*)  d_in[5];
    float*       out     = (float*)      d_out;

    const int n_in   = in_sizes[0];                 // 1024
    const long long N = (long long)in_sizes[2];     // 16384 (bias length)

    int chunks = (n_in + CHUNK_THREADS - 1) / CHUNK_THREADS;   // 8 for n_in=1024
    // clamp to scratch capacity (defensive; 256*8=2048 << 8192)
    while (out_size * chunks > MAX_PARTIALS && chunks > 1) chunks >>= 1;
    const int rows_per_chunk = CHUNK_THREADS;  // 1 load per thread
    (void)rows_per_chunk;

    gather_kernel<<<out_size * chunks, CHUNK_THREADS>>>(
        in_vals, W, in_idx, out_idx, n_in, chunks, N);

    const int ft = 256;
    finalize_kernel<<<(out_size + ft - 1) / ft, ft>>>(
        bias, act_ids, out_idx, out, out_size, chunks);
}